// round 1
// baseline (speedup 1.0000x reference)
#include <cuda_runtime.h>
#include <math.h>

#define WIDTH  128
#define HEIGHT 128
#define NEARP  0.1f
#define FARP   10.0f
#define EPSV   1e-8f
#define MAXB   4
#define MAXV   4096
#define MAXF   4096

// Scratch (no allocs allowed): per-vertex transformed data and per-triangle setup.
__device__ float4 g_vert[MAXB][MAXV];        // xs, ys, z_ndc, valid(0/1)
__device__ float  g_invw[MAXB][MAXV];        // 1/w_safe
__device__ float4 g_tri[MAXB][MAXF][4];      // 16 floats of triangle setup

__device__ void compute_mvp(const float* cf, const float* cc,
                            const float* tt, const float* rt, float* MVP) {
    // Rodrigues
    float r0 = rt[0], r1 = rt[1], r2 = rt[2];
    float theta = sqrtf(r0 * r0 + r1 * r1 + r2 * r2 + 1e-12f);
    float k0 = r0 / theta, k1 = r1 / theta, k2 = r2 / theta;
    float st = sinf(theta), ctv = cosf(theta);
    float K[9] = { 0.f, -k2,  k1,
                   k2,  0.f, -k0,
                  -k1,  k0,  0.f };
    float KK[9];
    for (int i = 0; i < 3; i++)
        for (int j = 0; j < 3; j++) {
            float s = 0.f;
            for (int k = 0; k < 3; k++) s += K[i * 3 + k] * K[k * 3 + j];
            KK[i * 3 + j] = s;
        }
    float R[9];
    for (int i = 0; i < 3; i++)
        for (int j = 0; j < 3; j++)
            R[i * 3 + j] = (i == j ? 1.f : 0.f) + st * K[i * 3 + j] + (1.f - ctv) * KK[i * 3 + j];

    // view = [[R^T, 0],[t, 1]] (row-vector convention)
    float Vw[16];
    for (int i = 0; i < 3; i++) {
        for (int j = 0; j < 3; j++) Vw[i * 4 + j] = R[j * 3 + i];
        Vw[i * 4 + 3] = 0.f;
    }
    Vw[12] = tt[0]; Vw[13] = tt[1]; Vw[14] = tt[2]; Vw[15] = 1.f;

    // perspective (already transposed layout)
    float fav = 0.5f * (cf[0] + cf[1]);
    float s = NEARP / fav;
    float right  = ((float)WIDTH - (cc[0] + 0.5f)) * s;
    float left   = -(cc[0] + 0.5f) * s;
    float top    = (cc[1] + 0.5f) * s;
    float bottom = -((float)HEIGHT - cc[1] + 0.5f) * s;
    float P[16];
    for (int i = 0; i < 16; i++) P[i] = 0.f;
    P[0]  = 2.f * NEARP / (right - left);
    P[5]  = 2.f * NEARP / (top - bottom);
    P[8]  = (right + left) / (right - left);
    P[9]  = (top + bottom) / (top - bottom);
    P[10] = -(FARP + NEARP) / (FARP - NEARP);
    P[11] = -1.f;
    P[14] = -2.f * FARP * NEARP / (FARP - NEARP);

    // MVP = view @ proj
    for (int i = 0; i < 4; i++)
        for (int j = 0; j < 4; j++) {
            float sij = 0.f;
            for (int k = 0; k < 4; k++) sij += Vw[i * 4 + k] * P[k * 4 + j];
            MVP[i * 4 + j] = sij;
        }
}

__global__ void vert_kernel(const float* __restrict__ v,
                            const float* __restrict__ cf,
                            const float* __restrict__ cc,
                            const float* __restrict__ tt,
                            const float* __restrict__ rt,
                            int Vn) {
    __shared__ float MVP[16];
    if (threadIdx.x == 0) compute_mvp(cf, cc, tt, rt, MVP);
    __syncthreads();
    int b = blockIdx.x;
    for (int i = threadIdx.x; i < Vn; i += blockDim.x) {
        const float* vp = v + ((size_t)b * Vn + i) * 3;
        float X = vp[0], Y = vp[1], Z = vp[2];
        float c0 = X * MVP[0] + Y * MVP[4] + Z * MVP[8]  + MVP[12];
        float c1 = X * MVP[1] + Y * MVP[5] + Z * MVP[9]  + MVP[13];
        float c2 = X * MVP[2] + Y * MVP[6] + Z * MVP[10] + MVP[14];
        float c3 = X * MVP[3] + Y * MVP[7] + Z * MVP[11] + MVP[15];
        bool valid = c3 > EPSV;
        float ws = valid ? c3 : 1.f;
        float nx = c0 / ws, ny = c1 / ws, nz = c2 / ws;
        float xs = (nx * 0.5f + 0.5f) * (float)WIDTH;
        float ys = (0.5f - ny * 0.5f) * (float)HEIGHT;
        g_vert[b][i] = make_float4(xs, ys, nz, valid ? 1.f : 0.f);
        g_invw[b][i] = 1.f / ws;
    }
}

__global__ void tri_kernel(const int* __restrict__ f, int Fn) {
    int b = blockIdx.y;
    int t = blockIdx.x * blockDim.x + threadIdx.x;
    if (t >= Fn) return;
    int i0 = f[t * 3 + 0], i1 = f[t * 3 + 1], i2 = f[t * 3 + 2];
    float4 A  = g_vert[b][i0];
    float4 Bv = g_vert[b][i1];
    float4 C  = g_vert[b][i2];
    float area = (Bv.x - A.x) * (C.y - A.y) - (Bv.y - A.y) * (C.x - A.x);
    bool va = fabsf(area) > EPSV;
    float area_safe = va ? area : 1.f;
    float inva = 1.f / area_safe;
    bool valid = (A.w != 0.f) && (Bv.w != 0.f) && (C.w != 0.f) && va;
    float za = A.z, zb = Bv.z, zc = C.z;
    if (!valid) {
        float qn = __int_as_float(0x7FC00000);  // NaN: fails z-range test -> never selected
        za = qn; zb = qn; zc = qn;
    }
    g_tri[b][t][0] = make_float4(A.x, A.y, Bv.x, Bv.y);
    g_tri[b][t][1] = make_float4(C.x, C.y, C.x - Bv.x, C.y - Bv.y);
    g_tri[b][t][2] = make_float4(A.x - C.x, A.y - C.y, Bv.x - A.x, Bv.y - A.y);
    g_tri[b][t][3] = make_float4(za, zb, zc, inva);
}

__global__ void raster_kernel(const int* __restrict__ f,
                              const float* __restrict__ vc,
                              const float* __restrict__ bg,
                              float* __restrict__ out,
                              int Fn) {
    extern __shared__ float4 s_tri[];  // Fn * 4 float4s
    int b = blockIdx.y;
    const float4* src = &g_tri[b][0][0];
    for (int i = threadIdx.x; i < Fn * 4; i += blockDim.x) s_tri[i] = src[i];
    __syncthreads();

    int p = blockIdx.x * blockDim.x + threadIdx.x;
    float x = (float)(p & (WIDTH - 1)) + 0.5f;
    float y = (float)(p >> 7) + 0.5f;  // WIDTH == 128

    float bestz = INFINITY;
    int   besti = -1;
    float bb0 = 0.f, bb1 = 0.f, bb2 = 0.f;

#pragma unroll 4
    for (int t = 0; t < Fn; t++) {
        float4 t0 = s_tri[t * 4 + 0];
        float4 t1 = s_tri[t * 4 + 1];
        float4 t2 = s_tri[t * 4 + 2];
        float4 t3 = s_tri[t * 4 + 3];
        // w0 = E(b,c), w1 = E(c,a), w2 = E(a,b) — same operand order as reference
        float w0 = t1.z * (y - t0.w) - t1.w * (x - t0.z);
        float w1 = t2.x * (y - t1.y) - t2.y * (x - t1.x);
        float w2 = t2.z * (y - t0.y) - t2.w * (x - t0.x);
        float inva = t3.w;
        float b0 = w0 * inva, b1 = w1 * inva, b2 = w2 * inva;
        float z = b0 * t3.x + b1 * t3.y + b2 * t3.z;  // NaN if invalid triangle
        bool inside = (b0 >= 0.f) && (b1 >= 0.f) && (b2 >= 0.f) &&
                      (z >= -1.f) && (z <= 1.f);
        if (inside && z < bestz) {  // strict < == argmin first-occurrence tie-break
            bestz = z; besti = t;
            bb0 = b0; bb1 = b1; bb2 = b2;
        }
    }

    float cr, cg, cb;
    if (besti < 0) {
        cr = bg[0]; cg = bg[1]; cb = bg[2];
    } else {
        int i0 = f[besti * 3 + 0], i1 = f[besti * 3 + 1], i2 = f[besti * 3 + 2];
        float iw0 = g_invw[b][i0], iw1 = g_invw[b][i1], iw2 = g_invw[b][i2];
        float q0 = bb0 * iw0, q1 = bb1 * iw1, q2 = bb2 * iw2;
        float den = q0 + q1 + q2;
        if (!(fabsf(den) > EPSV)) den = 1.f;
        cr = (q0 * vc[i0 * 3 + 0] + q1 * vc[i1 * 3 + 0] + q2 * vc[i2 * 3 + 0]) / den;
        cg = (q0 * vc[i0 * 3 + 1] + q1 * vc[i1 * 3 + 1] + q2 * vc[i2 * 3 + 1]) / den;
        cb = (q0 * vc[i0 * 3 + 2] + q1 * vc[i1 * 3 + 2] + q2 * vc[i2 * 3 + 2]) / den;
    }
    float* op = out + ((size_t)b * HEIGHT * WIDTH + p) * 3;
    op[0] = cr; op[1] = cg; op[2] = cb;
}

extern "C" void kernel_launch(void* const* d_in, const int* in_sizes, int n_in,
                              void* d_out, int out_size) {
    const float* v   = (const float*)d_in[0];
    const float* vc  = (const float*)d_in[1];
    const int*   f   = (const int*)d_in[2];
    const float* bg  = (const float*)d_in[3];
    const float* cf  = (const float*)d_in[4];
    const float* cc  = (const float*)d_in[5];
    const float* ct  = (const float*)d_in[6];
    const float* crt = (const float*)d_in[7];

    int Vn = in_sizes[1] / 3;
    int Fn = in_sizes[2] / 3;
    int Bn = in_sizes[0] / (3 * Vn);

    vert_kernel<<<Bn, 256>>>(v, cf, cc, ct, crt, Vn);

    dim3 tg((Fn + 255) / 256, Bn);
    tri_kernel<<<tg, 256>>>(f, Fn);

    size_t smem = (size_t)Fn * 4 * sizeof(float4);  // 64 KB @ Fn=1024
    cudaFuncSetAttribute(raster_kernel,
                         cudaFuncAttributeMaxDynamicSharedMemorySize, (int)smem);
    dim3 rg((HEIGHT * WIDTH + 127) / 128, Bn);
    raster_kernel<<<rg, 128, smem>>>(f, vc, bg, (float*)d_out, Fn);
}

// round 3
// speedup vs baseline: 2.0040x; 2.0040x over previous
#include <cuda_runtime.h>
#include <math.h>

#define WIDTH  128
#define HEIGHT 128
#define NEARP  0.1f
#define FARP   10.0f
#define EPSV   1e-8f

#define THREADS   512
#define PX_BLK    128          // pixels per block (one image row)
#define SLICES    4            // triangle slices per pixel
#define MAXV_S    1024
#define MAXF_S    1024

__device__ __forceinline__ void compute_mvp(const float* cf, const float* cc,
                                            const float* tt, const float* rt,
                                            float* MVP) {
    float r0 = rt[0], r1 = rt[1], r2 = rt[2];
    float theta = sqrtf(r0 * r0 + r1 * r1 + r2 * r2 + 1e-12f);
    float k0 = r0 / theta, k1 = r1 / theta, k2 = r2 / theta;
    float st = sinf(theta), ctv = cosf(theta);
    float K[9] = { 0.f, -k2,  k1,
                   k2,  0.f, -k0,
                  -k1,  k0,  0.f };
    float KK[9];
    for (int i = 0; i < 3; i++)
        for (int j = 0; j < 3; j++) {
            float s = 0.f;
            for (int k = 0; k < 3; k++) s += K[i * 3 + k] * K[k * 3 + j];
            KK[i * 3 + j] = s;
        }
    float R[9];
    for (int i = 0; i < 3; i++)
        for (int j = 0; j < 3; j++)
            R[i * 3 + j] = (i == j ? 1.f : 0.f) + st * K[i * 3 + j] + (1.f - ctv) * KK[i * 3 + j];

    float Vw[16];
    for (int i = 0; i < 3; i++) {
        for (int j = 0; j < 3; j++) Vw[i * 4 + j] = R[j * 3 + i];
        Vw[i * 4 + 3] = 0.f;
    }
    Vw[12] = tt[0]; Vw[13] = tt[1]; Vw[14] = tt[2]; Vw[15] = 1.f;

    float fav = 0.5f * (cf[0] + cf[1]);
    float s = NEARP / fav;
    float right  = ((float)WIDTH - (cc[0] + 0.5f)) * s;
    float left   = -(cc[0] + 0.5f) * s;
    float top    = (cc[1] + 0.5f) * s;
    float bottom = -((float)HEIGHT - cc[1] + 0.5f) * s;
    float P[16];
    for (int i = 0; i < 16; i++) P[i] = 0.f;
    P[0]  = 2.f * NEARP / (right - left);
    P[5]  = 2.f * NEARP / (top - bottom);
    P[8]  = (right + left) / (right - left);
    P[9]  = (top + bottom) / (top - bottom);
    P[10] = -(FARP + NEARP) / (FARP - NEARP);
    P[11] = -1.f;
    P[14] = -2.f * FARP * NEARP / (FARP - NEARP);

    for (int i = 0; i < 4; i++)
        for (int j = 0; j < 4; j++) {
            float sij = 0.f;
            for (int k = 0; k < 4; k++) sij += Vw[i * 4 + k] * P[k * 4 + j];
            MVP[i * 4 + j] = sij;
        }
}

// Single fused kernel: each block renders one image row; redundantly does
// vertex transform + triangle setup into its own shared memory (cheap),
// then 4-way triangle-sliced raster loop with packed (z,idx) argmin merge.
extern "C" __global__ void __launch_bounds__(THREADS, 1)
render_kernel(const float* __restrict__ v,
              const float* __restrict__ vc,
              const int*   __restrict__ f,
              const float* __restrict__ bg,
              const float* __restrict__ cf,
              const float* __restrict__ cc,
              const float* __restrict__ ct,
              const float* __restrict__ crt,
              float* __restrict__ out,
              int Vn, int Fn) {
    extern __shared__ char smem_raw[];
    float4* s_tri  = (float4*)smem_raw;                          // Fn*4 float4
    float4* s_vert = (float4*)(smem_raw + (size_t)Fn * 64);      // Vn float4 (xs,ys,z,invw)
    unsigned long long* s_red =
        (unsigned long long*)((char*)s_vert + (size_t)MAXV_S * 16);   // PX_BLK*SLICES
    float* s_valid = (float*)((char*)s_red + PX_BLK * SLICES * 8);    // Vn floats
    __shared__ float MVP[16];

    int tid = threadIdx.x;
    int b   = blockIdx.y;

    if (tid == 0) compute_mvp(cf, cc, ct, crt, MVP);
    __syncthreads();

    // ---- vertex transform ----
    for (int i = tid; i < Vn; i += THREADS) {
        const float* vp = v + ((size_t)b * Vn + i) * 3;
        float X = vp[0], Y = vp[1], Z = vp[2];
        float c0 = X * MVP[0] + Y * MVP[4] + Z * MVP[8]  + MVP[12];
        float c1 = X * MVP[1] + Y * MVP[5] + Z * MVP[9]  + MVP[13];
        float c2 = X * MVP[2] + Y * MVP[6] + Z * MVP[10] + MVP[14];
        float c3 = X * MVP[3] + Y * MVP[7] + Z * MVP[11] + MVP[15];
        bool valid = c3 > EPSV;
        float ws = valid ? c3 : 1.f;
        float nx = c0 / ws, ny = c1 / ws, nz = c2 / ws;
        float xs = (nx * 0.5f + 0.5f) * (float)WIDTH;
        float ys = (0.5f - ny * 0.5f) * (float)HEIGHT;
        s_vert[i]  = make_float4(xs, ys, nz, 1.f / ws);
        s_valid[i] = valid ? 1.f : 0.f;
    }
    __syncthreads();

    // ---- triangle setup ----
    for (int t = tid; t < Fn; t += THREADS) {
        int i0 = f[t * 3 + 0], i1 = f[t * 3 + 1], i2 = f[t * 3 + 2];
        float4 A  = s_vert[i0];
        float4 Bv = s_vert[i1];
        float4 C  = s_vert[i2];
        float area = (Bv.x - A.x) * (C.y - A.y) - (Bv.y - A.y) * (C.x - A.x);
        bool va = fabsf(area) > EPSV;
        float area_safe = va ? area : 1.f;
        float inva = 1.f / area_safe;
        bool valid = (s_valid[i0] != 0.f) && (s_valid[i1] != 0.f) &&
                     (s_valid[i2] != 0.f) && va;
        float za = A.z, zb = Bv.z, zc = C.z;
        if (!valid) {
            float qn = __int_as_float(0x7FC00000);   // NaN -> never selected
            za = qn; zb = qn; zc = qn;
        }
        s_tri[t * 4 + 0] = make_float4(A.x, A.y, Bv.x, Bv.y);
        s_tri[t * 4 + 1] = make_float4(C.x, C.y, C.x - Bv.x, C.y - Bv.y);
        s_tri[t * 4 + 2] = make_float4(A.x - C.x, A.y - C.y, Bv.x - A.x, Bv.y - A.y);
        s_tri[t * 4 + 3] = make_float4(za, zb, zc, inva);
    }
    __syncthreads();

    // ---- rasterize: thread = (slice, pixel) ----
    int px    = tid & (PX_BLK - 1);
    int slice = tid >> 7;                 // PX_BLK == 128
    float x = (float)px + 0.5f;
    float y = (float)blockIdx.x + 0.5f;   // one row per block

    int chunk  = (Fn + SLICES - 1) / SLICES;
    int tStart = slice * chunk;
    int tEnd   = min(tStart + chunk, Fn);

    float bestz = INFINITY;
    int   besti = -1;

#pragma unroll 4
    for (int t = tStart; t < tEnd; t++) {
        float4 t0 = s_tri[t * 4 + 0];
        float4 t1 = s_tri[t * 4 + 1];
        float4 t2 = s_tri[t * 4 + 2];
        float4 t3 = s_tri[t * 4 + 3];
        float w0 = t1.z * (y - t0.w) - t1.w * (x - t0.z);
        float w1 = t2.x * (y - t1.y) - t2.y * (x - t1.x);
        float w2 = t2.z * (y - t0.y) - t2.w * (x - t0.x);
        float inva = t3.w;
        float b0 = w0 * inva, b1 = w1 * inva, b2 = w2 * inva;
        float z = b0 * t3.x + b1 * t3.y + b2 * t3.z;   // NaN if invalid
        bool inside = (b0 >= 0.f) && (b1 >= 0.f) && (b2 >= 0.f) &&
                      (z >= -1.f) && (z <= 1.f);
        if (inside && z < bestz) { bestz = z; besti = t; }
    }

    // pack (orderable z, tri idx): lexicographic min == argmin first-index
    unsigned long long key = ~0ull;
    if (besti >= 0) {
        unsigned zu = __float_as_uint(bestz);
        zu = (zu & 0x80000000u) ? ~zu : (zu | 0x80000000u);
        key = ((unsigned long long)zu << 32) | (unsigned)besti;
    }
    s_red[px * SLICES + slice] = key;
    __syncthreads();

    // ---- merge + shade (first 128 threads) ----
    if (tid < PX_BLK) {
        int p = tid;
        unsigned long long k0 = s_red[p * SLICES + 0];
        unsigned long long k1 = s_red[p * SLICES + 1];
        unsigned long long k2 = s_red[p * SLICES + 2];
        unsigned long long k3 = s_red[p * SLICES + 3];
        unsigned long long best = min(min(k0, k1), min(k2, k3));

        float xp = (float)p + 0.5f;
        float cr, cg, cb;
        if ((unsigned)(best >> 32) == 0xFFFFFFFFu) {
            cr = bg[0]; cg = bg[1]; cb = bg[2];
        } else {
            int t = (int)(unsigned)best;
            float4 t0 = s_tri[t * 4 + 0];
            float4 t1 = s_tri[t * 4 + 1];
            float4 t2 = s_tri[t * 4 + 2];
            float4 t3 = s_tri[t * 4 + 3];
            float w0 = t1.z * (y - t0.w) - t1.w * (xp - t0.z);
            float w1 = t2.x * (y - t1.y) - t2.y * (xp - t1.x);
            float w2 = t2.z * (y - t0.y) - t2.w * (xp - t0.x);
            float inva = t3.w;
            float b0 = w0 * inva, b1 = w1 * inva, b2 = w2 * inva;
            int i0 = f[t * 3 + 0], i1 = f[t * 3 + 1], i2 = f[t * 3 + 2];
            float q0 = b0 * s_vert[i0].w;
            float q1 = b1 * s_vert[i1].w;
            float q2 = b2 * s_vert[i2].w;
            float den = q0 + q1 + q2;
            if (!(fabsf(den) > EPSV)) den = 1.f;
            cr = (q0 * vc[i0 * 3 + 0] + q1 * vc[i1 * 3 + 0] + q2 * vc[i2 * 3 + 0]) / den;
            cg = (q0 * vc[i0 * 3 + 1] + q1 * vc[i1 * 3 + 1] + q2 * vc[i2 * 3 + 1]) / den;
            cb = (q0 * vc[i0 * 3 + 2] + q1 * vc[i1 * 3 + 2] + q2 * vc[i2 * 3 + 2]) / den;
        }
        float* op = out + ((size_t)b * HEIGHT * WIDTH + (size_t)blockIdx.x * PX_BLK + p) * 3;
        op[0] = cr; op[1] = cg; op[2] = cb;
    }
}

extern "C" void kernel_launch(void* const* d_in, const int* in_sizes, int n_in,
                              void* d_out, int out_size) {
    const float* v   = (const float*)d_in[0];
    const float* vc  = (const float*)d_in[1];
    const int*   f   = (const int*)d_in[2];
    const float* bg  = (const float*)d_in[3];
    const float* cf  = (const float*)d_in[4];
    const float* cc  = (const float*)d_in[5];
    const float* ct  = (const float*)d_in[6];
    const float* crt = (const float*)d_in[7];

    int Vn = in_sizes[1] / 3;
    int Fn = in_sizes[2] / 3;
    int Bn = in_sizes[0] / (3 * Vn);

    size_t smem = (size_t)Fn * 64 + (size_t)MAXV_S * 16 +
                  (size_t)PX_BLK * SLICES * 8 + (size_t)MAXV_S * 4;
    static int smem_set = 0;
    if (!smem_set) {
        cudaFuncSetAttribute(render_kernel,
                             cudaFuncAttributeMaxDynamicSharedMemorySize,
                             (int)smem);
        smem_set = 1;
    }
    dim3 grid(HEIGHT * WIDTH / PX_BLK, Bn);
    render_kernel<<<grid, THREADS, smem>>>(v, vc, f, bg, cf, cc, ct, crt,
                                           (float*)d_out, Vn, Fn);
}

// round 4
// speedup vs baseline: 2.0328x; 1.0143x over previous
#include <cuda_runtime.h>
#include <math.h>

#define WIDTH  128
#define HEIGHT 128
#define NEARP  0.1f
#define FARP   10.0f
#define EPSV   1e-8f

#define THREADS   512
#define PX_BLK    64           // pixels per block (half an image row)
#define SLICES    8            // triangle slices per pixel

__device__ __forceinline__ void compute_mvp(const float* cf, const float* cc,
                                            const float* tt, const float* rt,
                                            float* MVP) {
    float r0 = rt[0], r1 = rt[1], r2 = rt[2];
    float theta = sqrtf(r0 * r0 + r1 * r1 + r2 * r2 + 1e-12f);
    float k0 = r0 / theta, k1 = r1 / theta, k2 = r2 / theta;
    float st = sinf(theta), ctv = cosf(theta);
    float K[9] = { 0.f, -k2,  k1,
                   k2,  0.f, -k0,
                  -k1,  k0,  0.f };
    float KK[9];
    for (int i = 0; i < 3; i++)
        for (int j = 0; j < 3; j++) {
            float s = 0.f;
            for (int k = 0; k < 3; k++) s += K[i * 3 + k] * K[k * 3 + j];
            KK[i * 3 + j] = s;
        }
    float R[9];
    for (int i = 0; i < 3; i++)
        for (int j = 0; j < 3; j++)
            R[i * 3 + j] = (i == j ? 1.f : 0.f) + st * K[i * 3 + j] + (1.f - ctv) * KK[i * 3 + j];

    float Vw[16];
    for (int i = 0; i < 3; i++) {
        for (int j = 0; j < 3; j++) Vw[i * 4 + j] = R[j * 3 + i];
        Vw[i * 4 + 3] = 0.f;
    }
    Vw[12] = tt[0]; Vw[13] = tt[1]; Vw[14] = tt[2]; Vw[15] = 1.f;

    float fav = 0.5f * (cf[0] + cf[1]);
    float s = NEARP / fav;
    float right  = ((float)WIDTH - (cc[0] + 0.5f)) * s;
    float left   = -(cc[0] + 0.5f) * s;
    float top    = (cc[1] + 0.5f) * s;
    float bottom = -((float)HEIGHT - cc[1] + 0.5f) * s;
    float P[16];
    for (int i = 0; i < 16; i++) P[i] = 0.f;
    P[0]  = 2.f * NEARP / (right - left);
    P[5]  = 2.f * NEARP / (top - bottom);
    P[8]  = (right + left) / (right - left);
    P[9]  = (top + bottom) / (top - bottom);
    P[10] = -(FARP + NEARP) / (FARP - NEARP);
    P[11] = -1.f;
    P[14] = -2.f * FARP * NEARP / (FARP - NEARP);

    for (int i = 0; i < 4; i++)
        for (int j = 0; j < 4; j++) {
            float sij = 0.f;
            for (int k = 0; k < 4; k++) sij += Vw[i * 4 + k] * P[k * 4 + j];
            MVP[i * 4 + j] = sij;
        }
}

// One fused kernel. Each block renders PX_BLK pixels (half a row); it
// redundantly does vertex transform + triangle setup into its own shared
// memory (cheap), then an 8-way triangle-sliced raster loop with packed
// (z,idx) argmin merge. SMEM sized so 2 blocks fit per SM.
extern "C" __global__ void __launch_bounds__(THREADS, 2)
render_kernel(const float* __restrict__ v,
              const float* __restrict__ vc,
              const int*   __restrict__ f,
              const float* __restrict__ bg,
              const float* __restrict__ cf,
              const float* __restrict__ cc,
              const float* __restrict__ ct,
              const float* __restrict__ crt,
              float* __restrict__ out,
              int Vn, int Fn) {
    extern __shared__ char smem_raw[];
    float4* s_tri  = (float4*)smem_raw;                              // Fn*4 float4
    float4* s_vert = (float4*)(smem_raw + (size_t)Fn * 64);          // Vn float4 (xs,ys,z,invw)
    float*  s_valid = (float*)((char*)s_vert + (size_t)Vn * 16);     // Vn floats
    unsigned long long* s_red =
        (unsigned long long*)((char*)s_valid + (size_t)Vn * 4);      // PX_BLK*SLICES
    __shared__ float MVP[16];

    int tid = threadIdx.x;
    int b   = blockIdx.y;

    if (tid == 0) compute_mvp(cf, cc, ct, crt, MVP);
    __syncthreads();

    // ---- vertex transform ----
    for (int i = tid; i < Vn; i += THREADS) {
        const float* vp = v + ((size_t)b * Vn + i) * 3;
        float X = vp[0], Y = vp[1], Z = vp[2];
        float c0 = X * MVP[0] + Y * MVP[4] + Z * MVP[8]  + MVP[12];
        float c1 = X * MVP[1] + Y * MVP[5] + Z * MVP[9]  + MVP[13];
        float c2 = X * MVP[2] + Y * MVP[6] + Z * MVP[10] + MVP[14];
        float c3 = X * MVP[3] + Y * MVP[7] + Z * MVP[11] + MVP[15];
        bool valid = c3 > EPSV;
        float ws = valid ? c3 : 1.f;
        float nx = c0 / ws, ny = c1 / ws, nz = c2 / ws;
        float xs = (nx * 0.5f + 0.5f) * (float)WIDTH;
        float ys = (0.5f - ny * 0.5f) * (float)HEIGHT;
        s_vert[i]  = make_float4(xs, ys, nz, 1.f / ws);
        s_valid[i] = valid ? 1.f : 0.f;
    }
    __syncthreads();

    // ---- triangle setup ----
    for (int t = tid; t < Fn; t += THREADS) {
        int i0 = f[t * 3 + 0], i1 = f[t * 3 + 1], i2 = f[t * 3 + 2];
        float4 A  = s_vert[i0];
        float4 Bv = s_vert[i1];
        float4 C  = s_vert[i2];
        float area = (Bv.x - A.x) * (C.y - A.y) - (Bv.y - A.y) * (C.x - A.x);
        bool va = fabsf(area) > EPSV;
        float area_safe = va ? area : 1.f;
        float inva = 1.f / area_safe;
        bool valid = (s_valid[i0] != 0.f) && (s_valid[i1] != 0.f) &&
                     (s_valid[i2] != 0.f) && va;
        float za = A.z, zb = Bv.z, zc = C.z;
        if (!valid) {
            float qn = __int_as_float(0x7FC00000);   // NaN -> never selected
            za = qn; zb = qn; zc = qn;
        }
        s_tri[t * 4 + 0] = make_float4(A.x, A.y, Bv.x, Bv.y);
        s_tri[t * 4 + 1] = make_float4(C.x, C.y, C.x - Bv.x, C.y - Bv.y);
        s_tri[t * 4 + 2] = make_float4(A.x - C.x, A.y - C.y, Bv.x - A.x, Bv.y - A.y);
        s_tri[t * 4 + 3] = make_float4(za, zb, zc, inva);
    }
    __syncthreads();

    // ---- rasterize: thread = (slice, pixel) ----
    int px    = tid & (PX_BLK - 1);
    int slice = tid / PX_BLK;
    int pglob = blockIdx.x * PX_BLK + px;            // linear pixel index
    float x = (float)(pglob & (WIDTH - 1)) + 0.5f;
    float y = (float)(pglob >> 7) + 0.5f;            // WIDTH == 128

    int chunk  = (Fn + SLICES - 1) / SLICES;
    int tStart = slice * chunk;
    int tEnd   = min(tStart + chunk, Fn);

    float bestz = INFINITY;
    int   besti = -1;

#pragma unroll 4
    for (int t = tStart; t < tEnd; t++) {
        float4 t0 = s_tri[t * 4 + 0];
        float4 t1 = s_tri[t * 4 + 1];
        float4 t2 = s_tri[t * 4 + 2];
        float4 t3 = s_tri[t * 4 + 3];
        float w0 = t1.z * (y - t0.w) - t1.w * (x - t0.z);
        float w1 = t2.x * (y - t1.y) - t2.y * (x - t1.x);
        float w2 = t2.z * (y - t0.y) - t2.w * (x - t0.x);
        float inva = t3.w;
        float b0 = w0 * inva, b1 = w1 * inva, b2 = w2 * inva;
        float z = b0 * t3.x + b1 * t3.y + b2 * t3.z;   // NaN if invalid
        bool inside = (b0 >= 0.f) && (b1 >= 0.f) && (b2 >= 0.f) &&
                      (z >= -1.f) && (z <= 1.f);
        if (inside && z < bestz) { bestz = z; besti = t; }
    }

    // pack (orderable z, tri idx): lexicographic min == argmin first-index
    unsigned long long key = ~0ull;
    if (besti >= 0) {
        unsigned zu = __float_as_uint(bestz);
        zu = (zu & 0x80000000u) ? ~zu : (zu | 0x80000000u);
        key = ((unsigned long long)zu << 32) | (unsigned)besti;
    }
    s_red[px * SLICES + slice] = key;
    __syncthreads();

    // ---- merge + shade (first PX_BLK threads) ----
    if (tid < PX_BLK) {
        int p = tid;
        unsigned long long best = s_red[p * SLICES + 0];
#pragma unroll
        for (int sl = 1; sl < SLICES; sl++)
            best = min(best, s_red[p * SLICES + sl]);

        int pg = blockIdx.x * PX_BLK + p;
        float xp = (float)(pg & (WIDTH - 1)) + 0.5f;
        float yp = (float)(pg >> 7) + 0.5f;
        float cr, cg, cb;
        if ((unsigned)(best >> 32) == 0xFFFFFFFFu) {
            cr = bg[0]; cg = bg[1]; cb = bg[2];
        } else {
            int t = (int)(unsigned)best;
            float4 t0 = s_tri[t * 4 + 0];
            float4 t1 = s_tri[t * 4 + 1];
            float4 t2 = s_tri[t * 4 + 2];
            float4 t3 = s_tri[t * 4 + 3];
            float w0 = t1.z * (yp - t0.w) - t1.w * (xp - t0.z);
            float w1 = t2.x * (yp - t1.y) - t2.y * (xp - t1.x);
            float w2 = t2.z * (yp - t0.y) - t2.w * (xp - t0.x);
            float inva = t3.w;
            float b0 = w0 * inva, b1 = w1 * inva, b2 = w2 * inva;
            int i0 = f[t * 3 + 0], i1 = f[t * 3 + 1], i2 = f[t * 3 + 2];
            float q0 = b0 * s_vert[i0].w;
            float q1 = b1 * s_vert[i1].w;
            float q2 = b2 * s_vert[i2].w;
            float den = q0 + q1 + q2;
            if (!(fabsf(den) > EPSV)) den = 1.f;
            cr = (q0 * vc[i0 * 3 + 0] + q1 * vc[i1 * 3 + 0] + q2 * vc[i2 * 3 + 0]) / den;
            cg = (q0 * vc[i0 * 3 + 1] + q1 * vc[i1 * 3 + 1] + q2 * vc[i2 * 3 + 1]) / den;
            cb = (q0 * vc[i0 * 3 + 2] + q1 * vc[i1 * 3 + 2] + q2 * vc[i2 * 3 + 2]) / den;
        }
        float* op = out + ((size_t)b * HEIGHT * WIDTH + pg) * 3;
        op[0] = cr; op[1] = cg; op[2] = cb;
    }
}

extern "C" void kernel_launch(void* const* d_in, const int* in_sizes, int n_in,
                              void* d_out, int out_size) {
    const float* v   = (const float*)d_in[0];
    const float* vc  = (const float*)d_in[1];
    const int*   f   = (const int*)d_in[2];
    const float* bg  = (const float*)d_in[3];
    const float* cf  = (const float*)d_in[4];
    const float* cc  = (const float*)d_in[5];
    const float* ct  = (const float*)d_in[6];
    const float* crt = (const float*)d_in[7];

    int Vn = in_sizes[1] / 3;
    int Fn = in_sizes[2] / 3;
    int Bn = in_sizes[0] / (3 * Vn);

    size_t smem = (size_t)Fn * 64 + (size_t)Vn * 16 + (size_t)Vn * 4 +
                  (size_t)PX_BLK * SLICES * 8;
    static int smem_set = 0;
    if (!smem_set) {
        cudaFuncSetAttribute(render_kernel,
                             cudaFuncAttributeMaxDynamicSharedMemorySize,
                             (int)smem);
        smem_set = 1;
    }
    dim3 grid(HEIGHT * WIDTH / PX_BLK, Bn);
    render_kernel<<<grid, THREADS, smem>>>(v, vc, f, bg, cf, cc, ct, crt,
                                           (float*)d_out, Vn, Fn);
}

// round 5
// speedup vs baseline: 2.1610x; 1.0631x over previous
#include <cuda_runtime.h>
#include <math.h>

#define WIDTH  128
#define HEIGHT 128
#define NEARP  0.1f
#define FARP   10.0f
#define EPSV   1e-8f

#define THREADS   512
#define PX_BLK    64     // pixels per block
#define PXT       32     // pixel-threads (each handles 2 pixels: p, p+32)
#define SLICES    16     // triangle slices

__device__ __forceinline__ void compute_mvp(const float* cf, const float* cc,
                                            const float* tt, const float* rt,
                                            float* MVP) {
    float r0 = rt[0], r1 = rt[1], r2 = rt[2];
    float theta = sqrtf(r0 * r0 + r1 * r1 + r2 * r2 + 1e-12f);
    float k0 = r0 / theta, k1 = r1 / theta, k2 = r2 / theta;
    float st = sinf(theta), ctv = cosf(theta);
    float K[9] = { 0.f, -k2,  k1,
                   k2,  0.f, -k0,
                  -k1,  k0,  0.f };
    float KK[9];
    for (int i = 0; i < 3; i++)
        for (int j = 0; j < 3; j++) {
            float s = 0.f;
            for (int k = 0; k < 3; k++) s += K[i * 3 + k] * K[k * 3 + j];
            KK[i * 3 + j] = s;
        }
    float R[9];
    for (int i = 0; i < 3; i++)
        for (int j = 0; j < 3; j++)
            R[i * 3 + j] = (i == j ? 1.f : 0.f) + st * K[i * 3 + j] + (1.f - ctv) * KK[i * 3 + j];

    float Vw[16];
    for (int i = 0; i < 3; i++) {
        for (int j = 0; j < 3; j++) Vw[i * 4 + j] = R[j * 3 + i];
        Vw[i * 4 + 3] = 0.f;
    }
    Vw[12] = tt[0]; Vw[13] = tt[1]; Vw[14] = tt[2]; Vw[15] = 1.f;

    float fav = 0.5f * (cf[0] + cf[1]);
    float s = NEARP / fav;
    float right  = ((float)WIDTH - (cc[0] + 0.5f)) * s;
    float left   = -(cc[0] + 0.5f) * s;
    float top    = (cc[1] + 0.5f) * s;
    float bottom = -((float)HEIGHT - cc[1] + 0.5f) * s;
    float P[16];
    for (int i = 0; i < 16; i++) P[i] = 0.f;
    P[0]  = 2.f * NEARP / (right - left);
    P[5]  = 2.f * NEARP / (top - bottom);
    P[8]  = (right + left) / (right - left);
    P[9]  = (top + bottom) / (top - bottom);
    P[10] = -(FARP + NEARP) / (FARP - NEARP);
    P[11] = -1.f;
    P[14] = -2.f * FARP * NEARP / (FARP - NEARP);

    for (int i = 0; i < 4; i++)
        for (int j = 0; j < 4; j++) {
            float sij = 0.f;
            for (int k = 0; k < 4; k++) sij += Vw[i * 4 + k] * P[k * 4 + j];
            MVP[i * 4 + j] = sij;
        }
}

// Fused renderer. Each block: 64 pixels. Triangle record is 40B
// (A.xy,B.xy | C.xy,za,zb | zc,inva); edge deltas are recomputed in-loop with
// the identical FADDs the old setup used, so all predicates stay bit-exact.
// Each thread evaluates 2 pixels per loaded triangle (x and x+32, same row).
extern "C" __global__ void __launch_bounds__(THREADS, 2)
render_kernel(const float* __restrict__ v,
              const float* __restrict__ vc,
              const int*   __restrict__ f,
              const float* __restrict__ bg,
              const float* __restrict__ cf,
              const float* __restrict__ cc,
              const float* __restrict__ ct,
              const float* __restrict__ crt,
              float* __restrict__ out,
              int Vn, int Fn) {
    extern __shared__ char smem_raw[];
    float4* s_triA = (float4*)smem_raw;                               // Fn
    float4* s_triB = (float4*)((char*)s_triA + (size_t)Fn * 16);      // Fn
    float2* s_triC = (float2*)((char*)s_triB + (size_t)Fn * 16);      // Fn
    float4* s_vert = (float4*)((char*)s_triC + (size_t)Fn * 8);       // Vn
    float*  s_valid = (float*)((char*)s_vert + (size_t)Vn * 16);      // Vn
    unsigned long long* s_red =
        (unsigned long long*)((char*)s_valid + (size_t)Vn * 4);       // SLICES*PX_BLK
    __shared__ float MVP[16];

    int tid = threadIdx.x;
    int b   = blockIdx.y;

    if (tid == 0) compute_mvp(cf, cc, ct, crt, MVP);
    __syncthreads();

    // ---- vertex transform ----
    for (int i = tid; i < Vn; i += THREADS) {
        const float* vp = v + ((size_t)b * Vn + i) * 3;
        float X = vp[0], Y = vp[1], Z = vp[2];
        float c0 = X * MVP[0] + Y * MVP[4] + Z * MVP[8]  + MVP[12];
        float c1 = X * MVP[1] + Y * MVP[5] + Z * MVP[9]  + MVP[13];
        float c2 = X * MVP[2] + Y * MVP[6] + Z * MVP[10] + MVP[14];
        float c3 = X * MVP[3] + Y * MVP[7] + Z * MVP[11] + MVP[15];
        bool valid = c3 > EPSV;
        float ws = valid ? c3 : 1.f;
        float nx = c0 / ws, ny = c1 / ws, nz = c2 / ws;
        float xs = (nx * 0.5f + 0.5f) * (float)WIDTH;
        float ys = (0.5f - ny * 0.5f) * (float)HEIGHT;
        s_vert[i]  = make_float4(xs, ys, nz, 1.f / ws);
        s_valid[i] = valid ? 1.f : 0.f;
    }
    __syncthreads();

    // ---- triangle setup (40B record) ----
    for (int t = tid; t < Fn; t += THREADS) {
        int i0 = f[t * 3 + 0], i1 = f[t * 3 + 1], i2 = f[t * 3 + 2];
        float4 A  = s_vert[i0];
        float4 Bv = s_vert[i1];
        float4 C  = s_vert[i2];
        float area = (Bv.x - A.x) * (C.y - A.y) - (Bv.y - A.y) * (C.x - A.x);
        bool va = fabsf(area) > EPSV;
        float area_safe = va ? area : 1.f;
        float inva = 1.f / area_safe;
        bool valid = (s_valid[i0] != 0.f) && (s_valid[i1] != 0.f) &&
                     (s_valid[i2] != 0.f) && va;
        float za = A.z, zb = Bv.z, zc = C.z;
        if (!valid) {
            float qn = __int_as_float(0x7FC00000);   // NaN -> never selected
            za = qn; zb = qn; zc = qn;
        }
        s_triA[t] = make_float4(A.x, A.y, Bv.x, Bv.y);
        s_triB[t] = make_float4(C.x, C.y, za, zb);
        s_triC[t] = make_float2(zc, inva);
    }
    __syncthreads();

    // ---- rasterize: thread = (slice, pixel-pair) ----
    int pxl   = tid & (PXT - 1);          // 0..31
    int slice = tid / PXT;                // 0..15
    int base  = blockIdx.x * PX_BLK;
    float y  = (float)(base >> 7) + 0.5f;                // WIDTH==128, block in one row
    float x0 = (float)((base & (WIDTH - 1)) + pxl) + 0.5f;
    float x1 = x0 + (float)PXT;

    int chunk  = (Fn + SLICES - 1) / SLICES;
    int tStart = slice * chunk;
    int tEnd   = min(tStart + chunk, Fn);

    float bz0 = INFINITY, bz1 = INFINITY;
    int   bi0 = -1,       bi1 = -1;

#pragma unroll 4
    for (int t = tStart; t < tEnd; t++) {
        float4 TA = s_triA[t];            // Ax,Ay,Bx,By
        float4 TB = s_triB[t];            // Cx,Cy,za,zb
        float2 TC = s_triC[t];            // zc,inva
        // edge deltas: identical FADDs to the reference's (q - p)
        float dCBx = TB.x - TA.z, dCBy = TB.y - TA.w;
        float dACx = TA.x - TB.x, dACy = TA.y - TB.y;
        float dBAx = TA.z - TA.x, dBAy = TA.w - TA.y;
        // shared y-subtractions
        float ymB = y - TA.w, ymC = y - TB.y, ymA = y - TA.y;
        float inva = TC.y;

        // pixel 0
        {
            float w0 = dCBx * ymB - dCBy * (x0 - TA.z);
            float w1 = dACx * ymC - dACy * (x0 - TB.x);
            float w2 = dBAx * ymA - dBAy * (x0 - TA.x);
            float b0 = w0 * inva, b1 = w1 * inva, b2 = w2 * inva;
            float z = b0 * TB.z + b1 * TB.w + b2 * TC.x;   // NaN if invalid
            bool inside = (b0 >= 0.f) && (b1 >= 0.f) && (b2 >= 0.f) &&
                          (z >= -1.f) && (z <= 1.f);
            if (inside && z < bz0) { bz0 = z; bi0 = t; }
        }
        // pixel 1
        {
            float w0 = dCBx * ymB - dCBy * (x1 - TA.z);
            float w1 = dACx * ymC - dACy * (x1 - TB.x);
            float w2 = dBAx * ymA - dBAy * (x1 - TA.x);
            float b0 = w0 * inva, b1 = w1 * inva, b2 = w2 * inva;
            float z = b0 * TB.z + b1 * TB.w + b2 * TC.x;
            bool inside = (b0 >= 0.f) && (b1 >= 0.f) && (b2 >= 0.f) &&
                          (z >= -1.f) && (z <= 1.f);
            if (inside && z < bz1) { bz1 = z; bi1 = t; }
        }
    }

    // pack (orderable z, tri idx): lexicographic min == argmin first-index
    unsigned long long k0 = ~0ull, k1 = ~0ull;
    if (bi0 >= 0) {
        unsigned zu = __float_as_uint(bz0);
        zu = (zu & 0x80000000u) ? ~zu : (zu | 0x80000000u);
        k0 = ((unsigned long long)zu << 32) | (unsigned)bi0;
    }
    if (bi1 >= 0) {
        unsigned zu = __float_as_uint(bz1);
        zu = (zu & 0x80000000u) ? ~zu : (zu | 0x80000000u);
        k1 = ((unsigned long long)zu << 32) | (unsigned)bi1;
    }
    s_red[slice * PX_BLK + pxl]        = k0;   // conflict-free: lane-consecutive
    s_red[slice * PX_BLK + pxl + PXT]  = k1;
    __syncthreads();

    // ---- merge + shade (first PX_BLK threads) ----
    if (tid < PX_BLK) {
        int p = tid;
        unsigned long long best = s_red[p];
#pragma unroll
        for (int sl = 1; sl < SLICES; sl++)
            best = min(best, s_red[sl * PX_BLK + p]);

        int pg = base + p;
        float xp = (float)(pg & (WIDTH - 1)) + 0.5f;
        float yp = (float)(pg >> 7) + 0.5f;
        float cr, cg, cb;
        if ((unsigned)(best >> 32) == 0xFFFFFFFFu) {
            cr = bg[0]; cg = bg[1]; cb = bg[2];
        } else {
            int t = (int)(unsigned)best;
            float4 TA = s_triA[t];
            float4 TB = s_triB[t];
            float2 TC = s_triC[t];
            float dCBx = TB.x - TA.z, dCBy = TB.y - TA.w;
            float dACx = TA.x - TB.x, dACy = TA.y - TB.y;
            float dBAx = TA.z - TA.x, dBAy = TA.w - TA.y;
            float w0 = dCBx * (yp - TA.w) - dCBy * (xp - TA.z);
            float w1 = dACx * (yp - TB.y) - dACy * (xp - TB.x);
            float w2 = dBAx * (yp - TA.y) - dBAy * (xp - TA.x);
            float inva = TC.y;
            float b0 = w0 * inva, b1 = w1 * inva, b2 = w2 * inva;
            int i0 = f[t * 3 + 0], i1 = f[t * 3 + 1], i2 = f[t * 3 + 2];
            float q0 = b0 * s_vert[i0].w;
            float q1 = b1 * s_vert[i1].w;
            float q2 = b2 * s_vert[i2].w;
            float den = q0 + q1 + q2;
            if (!(fabsf(den) > EPSV)) den = 1.f;
            cr = (q0 * vc[i0 * 3 + 0] + q1 * vc[i1 * 3 + 0] + q2 * vc[i2 * 3 + 0]) / den;
            cg = (q0 * vc[i0 * 3 + 1] + q1 * vc[i1 * 3 + 1] + q2 * vc[i2 * 3 + 1]) / den;
            cb = (q0 * vc[i0 * 3 + 2] + q1 * vc[i1 * 3 + 2] + q2 * vc[i2 * 3 + 2]) / den;
        }
        float* op = out + ((size_t)b * HEIGHT * WIDTH + pg) * 3;
        op[0] = cr; op[1] = cg; op[2] = cb;
    }
}

extern "C" void kernel_launch(void* const* d_in, const int* in_sizes, int n_in,
                              void* d_out, int out_size) {
    const float* v   = (const float*)d_in[0];
    const float* vc  = (const float*)d_in[1];
    const int*   f   = (const int*)d_in[2];
    const float* bg  = (const float*)d_in[3];
    const float* cf  = (const float*)d_in[4];
    const float* cc  = (const float*)d_in[5];
    const float* ct  = (const float*)d_in[6];
    const float* crt = (const float*)d_in[7];

    int Vn = in_sizes[1] / 3;
    int Fn = in_sizes[2] / 3;
    int Bn = in_sizes[0] / (3 * Vn);

    size_t smem = (size_t)Fn * 40 + (size_t)Vn * 20 +
                  (size_t)SLICES * PX_BLK * 8;
    static int smem_set = 0;
    if (!smem_set) {
        cudaFuncSetAttribute(render_kernel,
                             cudaFuncAttributeMaxDynamicSharedMemorySize,
                             (int)smem);
        smem_set = 1;
    }
    dim3 grid(HEIGHT * WIDTH / PX_BLK, Bn);
    render_kernel<<<grid, THREADS, smem>>>(v, vc, f, bg, cf, cc, ct, crt,
                                           (float*)d_out, Vn, Fn);
}

// round 6
// speedup vs baseline: 3.0274x; 1.4009x over previous
#include <cuda_runtime.h>
#include <math.h>

#define WIDTH  128
#define HEIGHT 128
#define NEARP  0.1f
#define FARP   10.0f
#define EPSV   1e-8f

#define THREADS   512
#define PX_BLK    64     // pixels per block (half a row)
#define PXT       32     // pixel-threads; each handles 2 pixels (p, p+32)
#define SLICES    16     // triangle slices (one warp each)
#define BBPAD     0.5f   // bbox safety pad (>> max fp rounding of edge fns)

__device__ __forceinline__ void compute_mvp(const float* cf, const float* cc,
                                            const float* tt, const float* rt,
                                            float* MVP) {
    float r0 = rt[0], r1 = rt[1], r2 = rt[2];
    float theta = sqrtf(r0 * r0 + r1 * r1 + r2 * r2 + 1e-12f);
    float k0 = r0 / theta, k1 = r1 / theta, k2 = r2 / theta;
    float st = sinf(theta), ctv = cosf(theta);
    float K[9] = { 0.f, -k2,  k1,
                   k2,  0.f, -k0,
                  -k1,  k0,  0.f };
    float KK[9];
    for (int i = 0; i < 3; i++)
        for (int j = 0; j < 3; j++) {
            float s = 0.f;
            for (int k = 0; k < 3; k++) s += K[i * 3 + k] * K[k * 3 + j];
            KK[i * 3 + j] = s;
        }
    float R[9];
    for (int i = 0; i < 3; i++)
        for (int j = 0; j < 3; j++)
            R[i * 3 + j] = (i == j ? 1.f : 0.f) + st * K[i * 3 + j] + (1.f - ctv) * KK[i * 3 + j];

    float Vw[16];
    for (int i = 0; i < 3; i++) {
        for (int j = 0; j < 3; j++) Vw[i * 4 + j] = R[j * 3 + i];
        Vw[i * 4 + 3] = 0.f;
    }
    Vw[12] = tt[0]; Vw[13] = tt[1]; Vw[14] = tt[2]; Vw[15] = 1.f;

    float fav = 0.5f * (cf[0] + cf[1]);
    float s = NEARP / fav;
    float right  = ((float)WIDTH - (cc[0] + 0.5f)) * s;
    float left   = -(cc[0] + 0.5f) * s;
    float top    = (cc[1] + 0.5f) * s;
    float bottom = -((float)HEIGHT - cc[1] + 0.5f) * s;
    float P[16];
    for (int i = 0; i < 16; i++) P[i] = 0.f;
    P[0]  = 2.f * NEARP / (right - left);
    P[5]  = 2.f * NEARP / (top - bottom);
    P[8]  = (right + left) / (right - left);
    P[9]  = (top + bottom) / (top - bottom);
    P[10] = -(FARP + NEARP) / (FARP - NEARP);
    P[11] = -1.f;
    P[14] = -2.f * FARP * NEARP / (FARP - NEARP);

    for (int i = 0; i < 4; i++)
        for (int j = 0; j < 4; j++) {
            float sij = 0.f;
            for (int k = 0; k < 4; k++) sij += Vw[i * 4 + k] * P[k * 4 + j];
            MVP[i * 4 + j] = sij;
        }
}

// Fused renderer with warp-uniform bbox rejection.
// Triangle record: bbox float4 + (A.xy,B.xy | C.xy,za,zb | zc,inva).
// Surviving triangles use the bit-exact reference arithmetic.
extern "C" __global__ void __launch_bounds__(THREADS, 2)
render_kernel(const float* __restrict__ v,
              const float* __restrict__ vc,
              const int*   __restrict__ f,
              const float* __restrict__ bg,
              const float* __restrict__ cf,
              const float* __restrict__ cc,
              const float* __restrict__ ct,
              const float* __restrict__ crt,
              float* __restrict__ out,
              int Vn, int Fn) {
    extern __shared__ char smem_raw[];
    float4* s_bbox = (float4*)smem_raw;                               // Fn
    float4* s_triA = (float4*)((char*)s_bbox + (size_t)Fn * 16);      // Fn
    float4* s_triB = (float4*)((char*)s_triA + (size_t)Fn * 16);      // Fn
    float2* s_triC = (float2*)((char*)s_triB + (size_t)Fn * 16);      // Fn
    float4* s_vert = (float4*)((char*)s_triC + (size_t)Fn * 8);       // Vn
    float*  s_valid = (float*)((char*)s_vert + (size_t)Vn * 16);      // Vn
    unsigned long long* s_red =
        (unsigned long long*)((char*)s_valid + (size_t)Vn * 4);       // SLICES*PX_BLK
    __shared__ float MVP[16];

    int tid = threadIdx.x;
    int b   = blockIdx.y;

    if (tid == 0) compute_mvp(cf, cc, ct, crt, MVP);
    __syncthreads();

    // ---- vertex transform ----
    for (int i = tid; i < Vn; i += THREADS) {
        const float* vp = v + ((size_t)b * Vn + i) * 3;
        float X = vp[0], Y = vp[1], Z = vp[2];
        float c0 = X * MVP[0] + Y * MVP[4] + Z * MVP[8]  + MVP[12];
        float c1 = X * MVP[1] + Y * MVP[5] + Z * MVP[9]  + MVP[13];
        float c2 = X * MVP[2] + Y * MVP[6] + Z * MVP[10] + MVP[14];
        float c3 = X * MVP[3] + Y * MVP[7] + Z * MVP[11] + MVP[15];
        bool valid = c3 > EPSV;
        float ws = valid ? c3 : 1.f;
        float nx = c0 / ws, ny = c1 / ws, nz = c2 / ws;
        float xs = (nx * 0.5f + 0.5f) * (float)WIDTH;
        float ys = (0.5f - ny * 0.5f) * (float)HEIGHT;
        s_vert[i]  = make_float4(xs, ys, nz, 1.f / ws);
        s_valid[i] = valid ? 1.f : 0.f;
    }
    __syncthreads();

    // ---- triangle setup ----
    for (int t = tid; t < Fn; t += THREADS) {
        int i0 = f[t * 3 + 0], i1 = f[t * 3 + 1], i2 = f[t * 3 + 2];
        float4 A  = s_vert[i0];
        float4 Bv = s_vert[i1];
        float4 C  = s_vert[i2];
        float area = (Bv.x - A.x) * (C.y - A.y) - (Bv.y - A.y) * (C.x - A.x);
        bool va = fabsf(area) > EPSV;
        float area_safe = va ? area : 1.f;
        float inva = 1.f / area_safe;
        bool valid = (s_valid[i0] != 0.f) && (s_valid[i1] != 0.f) &&
                     (s_valid[i2] != 0.f) && va;
        float za = A.z, zb = Bv.z, zc = C.z;
        if (!valid) {
            float qn = __int_as_float(0x7FC00000);   // NaN -> never selected
            za = qn; zb = qn; zc = qn;
        }
        float xmn = fminf(A.x, fminf(Bv.x, C.x)) - BBPAD;
        float xmx = fmaxf(A.x, fmaxf(Bv.x, C.x)) + BBPAD;
        float ymn = fminf(A.y, fminf(Bv.y, C.y)) - BBPAD;
        float ymx = fmaxf(A.y, fmaxf(Bv.y, C.y)) + BBPAD;
        s_bbox[t] = make_float4(xmn, xmx, ymn, ymx);
        s_triA[t] = make_float4(A.x, A.y, Bv.x, Bv.y);
        s_triB[t] = make_float4(C.x, C.y, za, zb);
        s_triC[t] = make_float2(zc, inva);
    }
    __syncthreads();

    // ---- rasterize: warp = slice, lanes = 32 pixel-pairs ----
    int pxl   = tid & (PXT - 1);          // lane 0..31
    int slice = tid / PXT;                // warp 0..15
    int base  = blockIdx.x * PX_BLK;
    float y   = (float)(base >> 7) + 0.5f;             // one row per block
    float xlo = (float)(base & (WIDTH - 1)) + 0.5f;    // block x-range
    float xhi = xlo + (float)(PX_BLK - 1);
    float x0  = xlo + (float)pxl;
    float x1  = x0 + (float)PXT;

    int chunk  = (Fn + SLICES - 1) / SLICES;
    int tStart = slice * chunk;
    int tEnd   = min(tStart + chunk, Fn);

    float bz0 = INFINITY, bz1 = INFINITY;
    int   bi0 = -1,       bi1 = -1;

#pragma unroll 2
    for (int t = tStart; t < tEnd; t++) {
        // warp-uniform bbox reject (conservative; cannot drop a selected tri)
        float4 bb = s_bbox[t];
        if (bb.z > y || bb.w < y || bb.x > xhi || bb.y < xlo) continue;

        float4 TA = s_triA[t];            // Ax,Ay,Bx,By
        float4 TB = s_triB[t];            // Cx,Cy,za,zb
        float2 TC = s_triC[t];            // zc,inva
        float dCBx = TB.x - TA.z, dCBy = TB.y - TA.w;
        float dACx = TA.x - TB.x, dACy = TA.y - TB.y;
        float dBAx = TA.z - TA.x, dBAy = TA.w - TA.y;
        float ymB = y - TA.w, ymC = y - TB.y, ymA = y - TA.y;
        float inva = TC.y;

        {   // pixel 0
            float w0 = dCBx * ymB - dCBy * (x0 - TA.z);
            float w1 = dACx * ymC - dACy * (x0 - TB.x);
            float w2 = dBAx * ymA - dBAy * (x0 - TA.x);
            float b0 = w0 * inva, b1 = w1 * inva, b2 = w2 * inva;
            float z = b0 * TB.z + b1 * TB.w + b2 * TC.x;   // NaN if invalid
            bool inside = (b0 >= 0.f) && (b1 >= 0.f) && (b2 >= 0.f) &&
                          (z >= -1.f) && (z <= 1.f);
            if (inside && z < bz0) { bz0 = z; bi0 = t; }
        }
        {   // pixel 1
            float w0 = dCBx * ymB - dCBy * (x1 - TA.z);
            float w1 = dACx * ymC - dACy * (x1 - TB.x);
            float w2 = dBAx * ymA - dBAy * (x1 - TA.x);
            float b0 = w0 * inva, b1 = w1 * inva, b2 = w2 * inva;
            float z = b0 * TB.z + b1 * TB.w + b2 * TC.x;
            bool inside = (b0 >= 0.f) && (b1 >= 0.f) && (b2 >= 0.f) &&
                          (z >= -1.f) && (z <= 1.f);
            if (inside && z < bz1) { bz1 = z; bi1 = t; }
        }
    }

    // pack (orderable z, tri idx): lexicographic min == argmin first-index
    unsigned long long k0 = ~0ull, k1 = ~0ull;
    if (bi0 >= 0) {
        unsigned zu = __float_as_uint(bz0);
        zu = (zu & 0x80000000u) ? ~zu : (zu | 0x80000000u);
        k0 = ((unsigned long long)zu << 32) | (unsigned)bi0;
    }
    if (bi1 >= 0) {
        unsigned zu = __float_as_uint(bz1);
        zu = (zu & 0x80000000u) ? ~zu : (zu | 0x80000000u);
        k1 = ((unsigned long long)zu << 32) | (unsigned)bi1;
    }
    s_red[slice * PX_BLK + pxl]       = k0;
    s_red[slice * PX_BLK + pxl + PXT] = k1;
    __syncthreads();

    // ---- merge + shade (first PX_BLK threads) ----
    if (tid < PX_BLK) {
        int p = tid;
        unsigned long long best = s_red[p];
#pragma unroll
        for (int sl = 1; sl < SLICES; sl++)
            best = min(best, s_red[sl * PX_BLK + p]);

        int pg = base + p;
        float xp = (float)(pg & (WIDTH - 1)) + 0.5f;
        float yp = (float)(pg >> 7) + 0.5f;
        float cr, cg, cb;
        if ((unsigned)(best >> 32) == 0xFFFFFFFFu) {
            cr = bg[0]; cg = bg[1]; cb = bg[2];
        } else {
            int t = (int)(unsigned)best;
            float4 TA = s_triA[t];
            float4 TB = s_triB[t];
            float2 TC = s_triC[t];
            float dCBx = TB.x - TA.z, dCBy = TB.y - TA.w;
            float dACx = TA.x - TB.x, dACy = TA.y - TB.y;
            float dBAx = TA.z - TA.x, dBAy = TA.w - TA.y;
            float w0 = dCBx * (yp - TA.w) - dCBy * (xp - TA.z);
            float w1 = dACx * (yp - TB.y) - dACy * (xp - TB.x);
            float w2 = dBAx * (yp - TA.y) - dBAy * (xp - TA.x);
            float inva = TC.y;
            float b0 = w0 * inva, b1 = w1 * inva, b2 = w2 * inva;
            int i0 = f[t * 3 + 0], i1 = f[t * 3 + 1], i2 = f[t * 3 + 2];
            float q0 = b0 * s_vert[i0].w;
            float q1 = b1 * s_vert[i1].w;
            float q2 = b2 * s_vert[i2].w;
            float den = q0 + q1 + q2;
            if (!(fabsf(den) > EPSV)) den = 1.f;
            cr = (q0 * vc[i0 * 3 + 0] + q1 * vc[i1 * 3 + 0] + q2 * vc[i2 * 3 + 0]) / den;
            cg = (q0 * vc[i0 * 3 + 1] + q1 * vc[i1 * 3 + 1] + q2 * vc[i2 * 3 + 1]) / den;
            cb = (q0 * vc[i0 * 3 + 2] + q1 * vc[i1 * 3 + 2] + q2 * vc[i2 * 3 + 2]) / den;
        }
        float* op = out + ((size_t)b * HEIGHT * WIDTH + pg) * 3;
        op[0] = cr; op[1] = cg; op[2] = cb;
    }
}

extern "C" void kernel_launch(void* const* d_in, const int* in_sizes, int n_in,
                              void* d_out, int out_size) {
    const float* v   = (const float*)d_in[0];
    const float* vc  = (const float*)d_in[1];
    const int*   f   = (const int*)d_in[2];
    const float* bg  = (const float*)d_in[3];
    const float* cf  = (const float*)d_in[4];
    const float* cc  = (const float*)d_in[5];
    const float* ct  = (const float*)d_in[6];
    const float* crt = (const float*)d_in[7];

    int Vn = in_sizes[1] / 3;
    int Fn = in_sizes[2] / 3;
    int Bn = in_sizes[0] / (3 * Vn);

    size_t smem = (size_t)Fn * 56 + (size_t)Vn * 20 +
                  (size_t)SLICES * PX_BLK * 8;
    static int smem_set = 0;
    if (!smem_set) {
        cudaFuncSetAttribute(render_kernel,
                             cudaFuncAttributeMaxDynamicSharedMemorySize,
                             (int)smem);
        smem_set = 1;
    }
    dim3 grid(HEIGHT * WIDTH / PX_BLK, Bn);
    render_kernel<<<grid, THREADS, smem>>>(v, vc, f, bg, cf, cc, ct, crt,
                                           (float*)d_out, Vn, Fn);
}

// round 7
// speedup vs baseline: 3.3604x; 1.1100x over previous
#include <cuda_runtime.h>
#include <math.h>

#define WIDTH  128
#define HEIGHT 128
#define NEARP  0.1f
#define FARP   10.0f
#define EPSV   1e-8f

#define THREADS   512
#define PX_BLK    64     // pixels per block (half a row)
#define PXT       32     // pixel-threads; each handles 2 pixels (p, p+32)
#define SLICES    16     // warps per block
#define BBPAD     0.5f   // bbox safety pad (>> max fp rounding of edge fns)

__device__ __forceinline__ void compute_mvp(const float* cf, const float* cc,
                                            const float* tt, const float* rt,
                                            float* MVP) {
    float r0 = rt[0], r1 = rt[1], r2 = rt[2];
    float theta = sqrtf(r0 * r0 + r1 * r1 + r2 * r2 + 1e-12f);
    float k0 = r0 / theta, k1 = r1 / theta, k2 = r2 / theta;
    float st = sinf(theta), ctv = cosf(theta);
    float K[9] = { 0.f, -k2,  k1,
                   k2,  0.f, -k0,
                  -k1,  k0,  0.f };
    float KK[9];
    for (int i = 0; i < 3; i++)
        for (int j = 0; j < 3; j++) {
            float s = 0.f;
            for (int k = 0; k < 3; k++) s += K[i * 3 + k] * K[k * 3 + j];
            KK[i * 3 + j] = s;
        }
    float R[9];
    for (int i = 0; i < 3; i++)
        for (int j = 0; j < 3; j++)
            R[i * 3 + j] = (i == j ? 1.f : 0.f) + st * K[i * 3 + j] + (1.f - ctv) * KK[i * 3 + j];

    float Vw[16];
    for (int i = 0; i < 3; i++) {
        for (int j = 0; j < 3; j++) Vw[i * 4 + j] = R[j * 3 + i];
        Vw[i * 4 + 3] = 0.f;
    }
    Vw[12] = tt[0]; Vw[13] = tt[1]; Vw[14] = tt[2]; Vw[15] = 1.f;

    float fav = 0.5f * (cf[0] + cf[1]);
    float s = NEARP / fav;
    float right  = ((float)WIDTH - (cc[0] + 0.5f)) * s;
    float left   = -(cc[0] + 0.5f) * s;
    float top    = (cc[1] + 0.5f) * s;
    float bottom = -((float)HEIGHT - cc[1] + 0.5f) * s;
    float P[16];
    for (int i = 0; i < 16; i++) P[i] = 0.f;
    P[0]  = 2.f * NEARP / (right - left);
    P[5]  = 2.f * NEARP / (top - bottom);
    P[8]  = (right + left) / (right - left);
    P[9]  = (top + bottom) / (top - bottom);
    P[10] = -(FARP + NEARP) / (FARP - NEARP);
    P[11] = -1.f;
    P[14] = -2.f * FARP * NEARP / (FARP - NEARP);

    for (int i = 0; i < 4; i++)
        for (int j = 0; j < 4; j++) {
            float sij = 0.f;
            for (int k = 0; k < 4; k++) sij += Vw[i * 4 + k] * P[k * 4 + j];
            MVP[i * 4 + j] = sij;
        }
}

// Fused renderer: setup -> block-level bbox compaction -> balanced branchless
// eval over compacted survivors -> (z,idx)-key argmin merge -> shade.
// Survivor eval uses arithmetic bit-identical to the reference.
extern "C" __global__ void __launch_bounds__(THREADS, 2)
render_kernel(const float* __restrict__ v,
              const float* __restrict__ vc,
              const int*   __restrict__ f,
              const float* __restrict__ bg,
              const float* __restrict__ cf,
              const float* __restrict__ cc,
              const float* __restrict__ ct,
              const float* __restrict__ crt,
              float* __restrict__ out,
              int Vn, int Fn) {
    extern __shared__ char smem_raw[];
    float4* s_bbox = (float4*)smem_raw;                               // Fn
    float4* s_triA = (float4*)((char*)s_bbox + (size_t)Fn * 16);      // Fn
    float4* s_triB = (float4*)((char*)s_triA + (size_t)Fn * 16);      // Fn
    float2* s_triC = (float2*)((char*)s_triB + (size_t)Fn * 16);      // Fn
    float4* s_vert = (float4*)((char*)s_triC + (size_t)Fn * 8);       // Vn
    float*  s_valid = (float*)((char*)s_vert + (size_t)Vn * 16);      // Vn
    unsigned long long* s_red =
        (unsigned long long*)((char*)s_valid + (size_t)Vn * 4);       // SLICES*PX_BLK
    int* s_list = (int*)((char*)s_red + (size_t)SLICES * PX_BLK * 8); // Fn
    __shared__ float MVP[16];
    __shared__ int s_cnt;

    int tid = threadIdx.x;
    int b   = blockIdx.y;

    if (tid == 0) { compute_mvp(cf, cc, ct, crt, MVP); s_cnt = 0; }
    __syncthreads();

    // ---- vertex transform ----
    for (int i = tid; i < Vn; i += THREADS) {
        const float* vp = v + ((size_t)b * Vn + i) * 3;
        float X = vp[0], Y = vp[1], Z = vp[2];
        float c0 = X * MVP[0] + Y * MVP[4] + Z * MVP[8]  + MVP[12];
        float c1 = X * MVP[1] + Y * MVP[5] + Z * MVP[9]  + MVP[13];
        float c2 = X * MVP[2] + Y * MVP[6] + Z * MVP[10] + MVP[14];
        float c3 = X * MVP[3] + Y * MVP[7] + Z * MVP[11] + MVP[15];
        bool valid = c3 > EPSV;
        float ws = valid ? c3 : 1.f;
        float nx = c0 / ws, ny = c1 / ws, nz = c2 / ws;
        float xs = (nx * 0.5f + 0.5f) * (float)WIDTH;
        float ys = (0.5f - ny * 0.5f) * (float)HEIGHT;
        s_vert[i]  = make_float4(xs, ys, nz, 1.f / ws);
        s_valid[i] = valid ? 1.f : 0.f;
    }
    __syncthreads();

    // ---- triangle setup ----
    for (int t = tid; t < Fn; t += THREADS) {
        int i0 = f[t * 3 + 0], i1 = f[t * 3 + 1], i2 = f[t * 3 + 2];
        float4 A  = s_vert[i0];
        float4 Bv = s_vert[i1];
        float4 C  = s_vert[i2];
        float area = (Bv.x - A.x) * (C.y - A.y) - (Bv.y - A.y) * (C.x - A.x);
        bool va = fabsf(area) > EPSV;
        float area_safe = va ? area : 1.f;
        float inva = 1.f / area_safe;
        bool valid = (s_valid[i0] != 0.f) && (s_valid[i1] != 0.f) &&
                     (s_valid[i2] != 0.f) && va;
        float za = A.z, zb = Bv.z, zc = C.z;
        if (!valid) {
            float qn = __int_as_float(0x7FC00000);   // NaN -> never selected
            za = qn; zb = qn; zc = qn;
        }
        float xmn = fminf(A.x, fminf(Bv.x, C.x)) - BBPAD;
        float xmx = fmaxf(A.x, fmaxf(Bv.x, C.x)) + BBPAD;
        float ymn = fminf(A.y, fminf(Bv.y, C.y)) - BBPAD;
        float ymx = fmaxf(A.y, fmaxf(Bv.y, C.y)) + BBPAD;
        s_bbox[t] = make_float4(xmn, xmx, ymn, ymx);
        s_triA[t] = make_float4(A.x, A.y, Bv.x, Bv.y);
        s_triB[t] = make_float4(C.x, C.y, za, zb);
        s_triC[t] = make_float2(zc, inva);
    }
    __syncthreads();

    // ---- bbox compaction for this block's (row, x-range) ----
    int   base = blockIdx.x * PX_BLK;
    float y    = (float)(base >> 7) + 0.5f;             // one row per block
    float xlo  = (float)(base & (WIDTH - 1)) + 0.5f;
    float xhi  = xlo + (float)(PX_BLK - 1);

    for (int t = tid; t < Fn; t += THREADS) {
        float4 bb = s_bbox[t];
        bool hit = (bb.z <= y) && (bb.w >= y) && (bb.x <= xhi) && (bb.y >= xlo);
        if (hit) {
            int slot = atomicAdd(&s_cnt, 1);   // unordered ok: key-min is order-invariant
            s_list[slot] = t;
        }
    }
    __syncthreads();
    int n = s_cnt;

    // ---- balanced branchless eval over survivors ----
    int pxl   = tid & (PXT - 1);          // lane 0..31
    int slice = tid / PXT;                // warp 0..15
    float x0  = xlo + (float)pxl;
    float x1  = x0 + (float)PXT;

    float bz0 = INFINITY, bz1 = INFINITY;
    int   bi0 = -1,       bi1 = -1;

    for (int i = slice; i < n; i += SLICES) {
        int t = s_list[i];                // lane-uniform broadcast
        float4 TA = s_triA[t];            // Ax,Ay,Bx,By
        float4 TB = s_triB[t];            // Cx,Cy,za,zb
        float2 TC = s_triC[t];            // zc,inva
        float dCBx = TB.x - TA.z, dCBy = TB.y - TA.w;
        float dACx = TA.x - TB.x, dACy = TA.y - TB.y;
        float dBAx = TA.z - TA.x, dBAy = TA.w - TA.y;
        float ymB = y - TA.w, ymC = y - TB.y, ymA = y - TA.y;
        float inva = TC.y;

        {   // pixel 0
            float w0 = dCBx * ymB - dCBy * (x0 - TA.z);
            float w1 = dACx * ymC - dACy * (x0 - TB.x);
            float w2 = dBAx * ymA - dBAy * (x0 - TA.x);
            float b0 = w0 * inva, b1 = w1 * inva, b2 = w2 * inva;
            float z = b0 * TB.z + b1 * TB.w + b2 * TC.x;   // NaN if invalid
            bool inside = (b0 >= 0.f) && (b1 >= 0.f) && (b2 >= 0.f) &&
                          (z >= -1.f) && (z <= 1.f);
            if (inside && z < bz0) { bz0 = z; bi0 = t; }
        }
        {   // pixel 1
            float w0 = dCBx * ymB - dCBy * (x1 - TA.z);
            float w1 = dACx * ymC - dACy * (x1 - TB.x);
            float w2 = dBAx * ymA - dBAy * (x1 - TA.x);
            float b0 = w0 * inva, b1 = w1 * inva, b2 = w2 * inva;
            float z = b0 * TB.z + b1 * TB.w + b2 * TC.x;
            bool inside = (b0 >= 0.f) && (b1 >= 0.f) && (b2 >= 0.f) &&
                          (z >= -1.f) && (z <= 1.f);
            if (inside && z < bz1) { bz1 = z; bi1 = t; }
        }
    }

    // pack (orderable z, tri idx): lexicographic min == argmin first-index
    unsigned long long k0 = ~0ull, k1 = ~0ull;
    if (bi0 >= 0) {
        unsigned zu = __float_as_uint(bz0);
        zu = (zu & 0x80000000u) ? ~zu : (zu | 0x80000000u);
        k0 = ((unsigned long long)zu << 32) | (unsigned)bi0;
    }
    if (bi1 >= 0) {
        unsigned zu = __float_as_uint(bz1);
        zu = (zu & 0x80000000u) ? ~zu : (zu | 0x80000000u);
        k1 = ((unsigned long long)zu << 32) | (unsigned)bi1;
    }
    s_red[slice * PX_BLK + pxl]       = k0;
    s_red[slice * PX_BLK + pxl + PXT] = k1;
    __syncthreads();

    // ---- merge + shade (first PX_BLK threads) ----
    if (tid < PX_BLK) {
        int p = tid;
        unsigned long long best = s_red[p];
#pragma unroll
        for (int sl = 1; sl < SLICES; sl++)
            best = min(best, s_red[sl * PX_BLK + p]);

        int pg = base + p;
        float xp = (float)(pg & (WIDTH - 1)) + 0.5f;
        float yp = (float)(pg >> 7) + 0.5f;
        float cr, cg, cb;
        if ((unsigned)(best >> 32) == 0xFFFFFFFFu) {
            cr = bg[0]; cg = bg[1]; cb = bg[2];
        } else {
            int t = (int)(unsigned)best;
            float4 TA = s_triA[t];
            float4 TB = s_triB[t];
            float2 TC = s_triC[t];
            float dCBx = TB.x - TA.z, dCBy = TB.y - TA.w;
            float dACx = TA.x - TB.x, dACy = TA.y - TB.y;
            float dBAx = TA.z - TA.x, dBAy = TA.w - TA.y;
            float w0 = dCBx * (yp - TA.w) - dCBy * (xp - TA.z);
            float w1 = dACx * (yp - TB.y) - dACy * (xp - TB.x);
            float w2 = dBAx * (yp - TA.y) - dBAy * (xp - TA.x);
            float inva = TC.y;
            float b0 = w0 * inva, b1 = w1 * inva, b2 = w2 * inva;
            int i0 = f[t * 3 + 0], i1 = f[t * 3 + 1], i2 = f[t * 3 + 2];
            float q0 = b0 * s_vert[i0].w;
            float q1 = b1 * s_vert[i1].w;
            float q2 = b2 * s_vert[i2].w;
            float den = q0 + q1 + q2;
            if (!(fabsf(den) > EPSV)) den = 1.f;
            cr = (q0 * vc[i0 * 3 + 0] + q1 * vc[i1 * 3 + 0] + q2 * vc[i2 * 3 + 0]) / den;
            cg = (q0 * vc[i0 * 3 + 1] + q1 * vc[i1 * 3 + 1] + q2 * vc[i2 * 3 + 1]) / den;
            cb = (q0 * vc[i0 * 3 + 2] + q1 * vc[i1 * 3 + 2] + q2 * vc[i2 * 3 + 2]) / den;
        }
        float* op = out + ((size_t)b * HEIGHT * WIDTH + pg) * 3;
        op[0] = cr; op[1] = cg; op[2] = cb;
    }
}

extern "C" void kernel_launch(void* const* d_in, const int* in_sizes, int n_in,
                              void* d_out, int out_size) {
    const float* v   = (const float*)d_in[0];
    const float* vc  = (const float*)d_in[1];
    const int*   f   = (const int*)d_in[2];
    const float* bg  = (const float*)d_in[3];
    const float* cf  = (const float*)d_in[4];
    const float* cc  = (const float*)d_in[5];
    const float* ct  = (const float*)d_in[6];
    const float* crt = (const float*)d_in[7];

    int Vn = in_sizes[1] / 3;
    int Fn = in_sizes[2] / 3;
    int Bn = in_sizes[0] / (3 * Vn);

    size_t smem = (size_t)Fn * 56 + (size_t)Vn * 20 +
                  (size_t)SLICES * PX_BLK * 8 + (size_t)Fn * 4;
    static int smem_set = 0;
    if (!smem_set) {
        cudaFuncSetAttribute(render_kernel,
                             cudaFuncAttributeMaxDynamicSharedMemorySize,
                             (int)smem);
        smem_set = 1;
    }
    dim3 grid(HEIGHT * WIDTH / PX_BLK, Bn);
    render_kernel<<<grid, THREADS, smem>>>(v, vc, f, bg, cf, cc, ct, crt,
                                           (float*)d_out, Vn, Fn);
}